// round 1
// baseline (speedup 1.0000x reference)
#include <cuda_runtime.h>
#include <cstdint>

// Problem constants
#define NB   4096
#define TT   256
#define FF   32
#define HH1  64
#define HH2  32
#define NTO  3
#define BB   32        // batch elements per block
#define NTHR 256
#define NBLK (NB / BB) // 128

// Shared memory layout (floats)
//   sW1[96][256]  layer1 combined weights (k<32: W_ih1, k>=32: W_hh1), columns permuted
//   sW2[96][128]  layer2 combined weights (k<64: W_ih2, k>=64: W_hh2), columns permuted
//   sB1[256], sB2[128]  combined biases, same column permutation
//   sA[128][64]   duplicated activations: rows 0..31 = x_t, 32..95 = h1, 96..127 = h2,
//                 cols store each value twice: sA[k][2b] == sA[k][2b+1]
#define SW1_ELEMS (96 * 256)
#define SW2_ELEMS (96 * 128)
#define SA_OFF    (SW1_ELEMS + SW2_ELEMS + 256 + 128)
#define SMEM_FLOATS (SA_OFF + 128 * 64)
#define SMEM_BYTES  (SMEM_FLOATS * 4)

// Packed fp32x2 FMA (Blackwell FFMA2) — d = a*b + d on two lanes
__device__ __forceinline__ void fma2(uint64_t& d, uint64_t a, uint64_t b) {
    asm("fma.rn.f32x2 %0, %1, %2, %0;" : "+l"(d) : "l"(a), "l"(b));
}
__device__ __forceinline__ float2 u2f2(uint64_t u) {
    float2 f; asm("mov.b64 {%0, %1}, %2;" : "=f"(f.x), "=f"(f.y) : "l"(u)); return f;
}
__device__ __forceinline__ uint64_t f2u2(float x, float y) {
    uint64_t u; asm("mov.b64 %0, {%1, %2};" : "=l"(u) : "f"(x), "f"(y)); return u;
}
__device__ __forceinline__ float sigf(float x) {
    return 1.0f / (1.0f + __expf(-x));
}
__device__ __forceinline__ float tanhx(float x) {
    // tanh(x) = 2*sigmoid(2x) - 1 ; accurate ex2/rcp path (~1e-7 rel), fast
    return 2.0f / (1.0f + __expf(-2.0f * x)) - 1.0f;
}

__global__ void __launch_bounds__(NTHR, 1)
lstm_fused_kernel(const float* __restrict__ x,
                  const float* __restrict__ Wih1, const float* __restrict__ Whh1,
                  const float* __restrict__ bih1, const float* __restrict__ bhh1,
                  const float* __restrict__ Wih2, const float* __restrict__ Whh2,
                  const float* __restrict__ bih2, const float* __restrict__ bhh2,
                  const float* __restrict__ Whead, const float* __restrict__ bhead,
                  float* __restrict__ out)
{
    extern __shared__ float sm[];
    float* sW1 = sm;
    float* sW2 = sW1 + SW1_ELEMS;
    float* sB1 = sW2 + SW2_ELEMS;
    float* sB2 = sB1 + 256;
    float* sA  = sB2 + 128;

    const int tid = threadIdx.x;

    // ---- One-time: load + permute weights into shared ----
    // Column permutation: c = jp*8 + gate*2 + jl, where j = jp*2 + jl.
    // So each 8-float group holds [i_j0,i_j1, f_j0,f_j1, g_j0,g_j1, o_j0,o_j1].
    for (int idx = tid; idx < SW1_ELEMS; idx += NTHR) {
        int k = idx >> 8, c = idx & 255;
        int jp = c >> 3, gate = (c >> 1) & 3, jl = c & 1;
        int g = gate * HH1 + jp * 2 + jl;
        sW1[idx] = (k < FF) ? Wih1[g * FF + k] : Whh1[g * HH1 + (k - FF)];
    }
    for (int idx = tid; idx < SW2_ELEMS; idx += NTHR) {
        int k = idx >> 7, c = idx & 127;
        int jp = c >> 3, gate = (c >> 1) & 3, jl = c & 1;
        int g = gate * HH2 + jp * 2 + jl;
        sW2[idx] = (k < HH1) ? Wih2[g * HH1 + k] : Whh2[g * HH2 + (k - HH1)];
    }
    if (tid < 256) {
        int c = tid;
        int jp = c >> 3, gate = (c >> 1) & 3, jl = c & 1;
        int g = gate * HH1 + jp * 2 + jl;
        sB1[c] = bih1[g] + bhh1[g];
    }
    if (tid < 128) {
        int c = tid;
        int jp = c >> 3, gate = (c >> 1) & 3, jl = c & 1;
        int g = gate * HH2 + jp * 2 + jl;
        sB2[c] = bih2[g] + bhh2[g];
    }
    // Zero h1/h2 rows (rows 32..127)
    for (int idx = tid; idx < 96 * 64; idx += NTHR) sA[32 * 64 + idx] = 0.0f;

    // ---- Thread mappings ----
    // Layer1: 8 b-tiles (4 batch each) x 32 j-pairs = 256 threads
    const int bt1 = tid & 7, jp1 = tid >> 3;
    // Layer2: 16 b-tiles (2 batch each) x 16 j-pairs = 256 threads
    const int bt2 = tid & 15, jp2 = tid >> 4;
    // x loader: 32 batch x 8 float4-chunks
    const int xb = tid >> 3, xf = tid & 7;

    const float* xp = x + ((size_t)(blockIdx.x * BB + xb) * TT) * FF + xf * 4;
    float4 xr = *(const float4*)xp;   // prefetch x_0

    uint64_t c1r[4] = {0, 0, 0, 0};   // cell state layer1: (c_j0,c_j1) per b
    uint64_t c2r[2] = {0, 0};         // cell state layer2

    const float* w1p = sW1 + jp1 * 8;
    const float* a1p = sA  + 8 * bt1;            // cols 2*(4*bt1) .. +7 (4 b's dup)
    const float* w2p = sW2 + jp2 * 8;
    const float* a2p = sA  + 32 * 64 + 4 * bt2;  // rows 32.., cols 2*(2*bt2) .. +3

    for (int t = 0; t < TT; t++) {
        // ---- store x_t duplicated into sA rows 0..31 ----
        {
            float v[4] = {xr.x, xr.y, xr.z, xr.w};
            #pragma unroll
            for (int c = 0; c < 4; c++)
                *(float2*)&sA[(xf * 4 + c) * 64 + 2 * xb] = make_float2(v[c], v[c]);
        }
        if (t + 1 < TT) xr = *(const float4*)(xp + (size_t)(t + 1) * FF);
        __syncthreads();   // S1: x_t + h2_{t-1} visible; everyone past prior reads

        // ---- Layer 1: gates[b][i,f,g,o] packed over (j0,j1) ----
        uint64_t acc[4][4];
        {
            ulonglong2 bA = *(const ulonglong2*)&sB1[jp1 * 8];
            ulonglong2 bBv = *(const ulonglong2*)&sB1[jp1 * 8 + 4];
            #pragma unroll
            for (int b = 0; b < 4; b++) {
                acc[b][0] = bA.x; acc[b][1] = bA.y; acc[b][2] = bBv.x; acc[b][3] = bBv.y;
            }
        }
        #pragma unroll 4
        for (int k = 0; k < 96; k++) {
            ulonglong2 w0 = *(const ulonglong2*)(w1p + k * 256);
            ulonglong2 w1 = *(const ulonglong2*)(w1p + k * 256 + 4);
            ulonglong2 a0 = *(const ulonglong2*)(a1p + k * 64);
            ulonglong2 a1 = *(const ulonglong2*)(a1p + k * 64 + 4);
            uint64_t ab[4] = {a0.x, a0.y, a1.x, a1.y};
            uint64_t wg[4] = {w0.x, w0.y, w1.x, w1.y};
            #pragma unroll
            for (int b = 0; b < 4; b++) {
                #pragma unroll
                for (int g = 0; g < 4; g++) fma2(acc[b][g], ab[b], wg[g]);
            }
        }
        float h1v[4][2];
        #pragma unroll
        for (int b = 0; b < 4; b++) {
            float2 iv = u2f2(acc[b][0]);
            float2 fv = u2f2(acc[b][1]);
            float2 gv = u2f2(acc[b][2]);
            float2 ov = u2f2(acc[b][3]);
            float2 cv = u2f2(c1r[b]);
            float c0 = sigf(fv.x) * cv.x + sigf(iv.x) * tanhx(gv.x);
            float c1 = sigf(fv.y) * cv.y + sigf(iv.y) * tanhx(gv.y);
            c1r[b] = f2u2(c0, c1);
            h1v[b][0] = sigf(ov.x) * tanhx(c0);
            h1v[b][1] = sigf(ov.y) * tanhx(c1);
        }
        __syncthreads();   // S2: all threads done reading h1_{t-1}
        #pragma unroll
        for (int b = 0; b < 4; b++) {
            int col = 2 * (4 * bt1 + b);
            *(float2*)&sA[(32 + jp1 * 2) * 64 + col]     = make_float2(h1v[b][0], h1v[b][0]);
            *(float2*)&sA[(32 + jp1 * 2 + 1) * 64 + col] = make_float2(h1v[b][1], h1v[b][1]);
        }
        __syncthreads();   // S3: h1_t visible

        // ---- Layer 2 ----
        uint64_t acc2[2][4];
        {
            ulonglong2 bA = *(const ulonglong2*)&sB2[jp2 * 8];
            ulonglong2 bBv = *(const ulonglong2*)&sB2[jp2 * 8 + 4];
            #pragma unroll
            for (int b = 0; b < 2; b++) {
                acc2[b][0] = bA.x; acc2[b][1] = bA.y; acc2[b][2] = bBv.x; acc2[b][3] = bBv.y;
            }
        }
        #pragma unroll 4
        for (int k = 0; k < 96; k++) {
            ulonglong2 w0 = *(const ulonglong2*)(w2p + k * 128);
            ulonglong2 w1 = *(const ulonglong2*)(w2p + k * 128 + 4);
            ulonglong2 a0 = *(const ulonglong2*)(a2p + k * 64);
            uint64_t ab[2] = {a0.x, a0.y};
            uint64_t wg[4] = {w0.x, w0.y, w1.x, w1.y};
            #pragma unroll
            for (int b = 0; b < 2; b++) {
                #pragma unroll
                for (int g = 0; g < 4; g++) fma2(acc2[b][g], ab[b], wg[g]);
            }
        }
        float h2v[2][2];
        #pragma unroll
        for (int b = 0; b < 2; b++) {
            float2 iv = u2f2(acc2[b][0]);
            float2 fv = u2f2(acc2[b][1]);
            float2 gv = u2f2(acc2[b][2]);
            float2 ov = u2f2(acc2[b][3]);
            float2 cv = u2f2(c2r[b]);
            float c0 = sigf(fv.x) * cv.x + sigf(iv.x) * tanhx(gv.x);
            float c1 = sigf(fv.y) * cv.y + sigf(iv.y) * tanhx(gv.y);
            c2r[b] = f2u2(c0, c1);
            h2v[b][0] = sigf(ov.x) * tanhx(c0);
            h2v[b][1] = sigf(ov.y) * tanhx(c1);
        }
        __syncthreads();   // S4: all threads done reading h2_{t-1}
        #pragma unroll
        for (int b = 0; b < 2; b++) {
            int col = 2 * (2 * bt2 + b);
            *(float2*)&sA[(96 + jp2 * 2) * 64 + col]     = make_float2(h2v[b][0], h2v[b][0]);
            *(float2*)&sA[(96 + jp2 * 2 + 1) * 64 + col] = make_float2(h2v[b][1], h2v[b][1]);
        }
    }
    __syncthreads();   // final h2 visible

    // ---- Head: out[b][n] = h2[b] . W_head[n] + b_head[n] ----
    if (tid < BB * NTO) {
        int b = tid / NTO, n = tid % NTO;
        float accv = bhead[n];
        #pragma unroll
        for (int j = 0; j < HH2; j++)
            accv += sA[(96 + j) * 64 + 2 * b] * Whead[n * HH2 + j];
        out[(size_t)(blockIdx.x * BB + b) * NTO + n] = accv;
    }
}

extern "C" void kernel_launch(void* const* d_in, const int* in_sizes, int n_in,
                              void* d_out, int out_size) {
    (void)in_sizes; (void)n_in; (void)out_size;
    const float* x     = (const float*)d_in[0];
    const float* Wih1  = (const float*)d_in[1];
    const float* Whh1  = (const float*)d_in[2];
    const float* bih1  = (const float*)d_in[3];
    const float* bhh1  = (const float*)d_in[4];
    const float* Wih2  = (const float*)d_in[5];
    const float* Whh2  = (const float*)d_in[6];
    const float* bih2  = (const float*)d_in[7];
    const float* bhh2  = (const float*)d_in[8];
    const float* Whead = (const float*)d_in[9];
    const float* bhead = (const float*)d_in[10];
    float* out = (float*)d_out;

    cudaFuncSetAttribute(lstm_fused_kernel,
                         cudaFuncAttributeMaxDynamicSharedMemorySize, SMEM_BYTES);
    lstm_fused_kernel<<<NBLK, NTHR, SMEM_BYTES>>>(
        x, Wih1, Whh1, bih1, bhh1, Wih2, Whh2, bih2, bhh2, Whead, bhead, out);
}